// round 2
// baseline (speedup 1.0000x reference)
#include <cuda_runtime.h>
#include <cuda_bf16.h>
#include <cuda_pipeline.h>
#include <math.h>

#define V_   32000
#define CHI_ 64
#define T_   512
#define B_   8
#define BT_  4096
#define NVB_ 500   // 32000 / 64 v-tiles
#define LN_EPS_ 1e-5f

// ---------------- scratch (static device memory; no allocations) ----------------
__device__ float g_ml[T_ * CHI_];
__device__ float g_mr[T_ * CHI_];
__device__ float g_HM[B_ * T_ * CHI_];          // h_mod[b][t][i]
__device__ float g_pmax[(size_t)BT_ * NVB_];    // per (row, v-tile) partial max
__device__ float g_psum[(size_t)BT_ * NVB_];    // per (row, v-tile) partial sum-exp
__device__ float g_tgt[BT_];                    // logit at target per row
__device__ float g_rowloss[BT_];

// ---------------- kernel 1: modulators ml, mr ----------------
// pos_emb(512x64) @ W1(64x128)+b1 -> gelu(exact) -> @W2(128x128)+b2 -> 1+0.5*tanh
__global__ void k_mod(const float* __restrict__ pos_embed,
                      const float* __restrict__ W1, const float* __restrict__ b1,
                      const float* __restrict__ W2, const float* __restrict__ b2) {
    int t = blockIdx.x;
    int k = threadIdx.x;             // 128 threads
    __shared__ float sp[64];
    __shared__ float sm[128];
    if (k < 64) sp[k] = pos_embed[t * 64 + k];
    __syncthreads();
    float s = b1[k];
#pragma unroll
    for (int p = 0; p < 64; p++) s += sp[p] * W1[p * 128 + k];
    float g = 0.5f * s * (1.0f + erff(s * 0.7071067811865476f));
    sm[k] = g;
    __syncthreads();
    float m = b2[k];
#pragma unroll
    for (int q = 0; q < 128; q++) m += sm[q] * W2[q * 128 + k];
    float v = 1.0f + 0.5f * tanhf(m);
    if (k < 64) g_ml[t * 64 + k] = v;
    else        g_mr[t * 64 + (k - 64)] = v;
}

// ---------------- kernel 2: sequential scan (8 blocks, one per batch) ----------------
// h_mod = h*ml_t (stored to g_HM); h_new = LN((h_mod @ core[:,x_t,:]) * mr_t)
// core slice (64x64 = 16KB) prefetched 2 steps ahead via cp.async (indices are input-only).
__global__ void __launch_bounds__(128) k_scan(const int* __restrict__ input_ids,
                                              const float* __restrict__ core,
                                              const float* __restrict__ h0,
                                              const float* __restrict__ ln_gamma,
                                              const float* __restrict__ ln_beta) {
    extern __shared__ float sl[];    // 3 * 4096 floats (3 x 16KB slice buffers)
    __shared__ float sh_h[64];
    __shared__ float sh_hm[64];
    __shared__ float part[2][64];
    __shared__ float red[4];

    int b = blockIdx.x;
    int tid = threadIdx.x;
    int j = tid & 63, half = tid >> 6;

    if (half == 0) sh_h[j] = h0[j];

    // prefetch slices for t = 0, 1
    for (int pf = 0; pf < 2; pf++) {
        int x = input_ids[b * T_ + pf];
        const float* src = core + (size_t)x * 64;
        float* dst = sl + pf * 4096;
        for (int c = tid; c < 1024; c += 128) {
            int i = c >> 4, q = c & 15;
            __pipeline_memcpy_async(dst + i * 64 + q * 4,
                                    src + (size_t)i * V_ * 64 + q * 4, 16);
        }
        __pipeline_commit();
    }

    for (int t = 0; t < T_; t++) {
        __pipeline_wait_prior(1);    // slice for t complete
        __syncthreads();

        // prefetch t+2
        {
            int tn = t + 2;
            if (tn < T_) {
                int x = input_ids[b * T_ + tn];
                const float* src = core + (size_t)x * 64;
                float* dst = sl + (tn % 3) * 4096;
                for (int c = tid; c < 1024; c += 128) {
                    int i = c >> 4, q = c & 15;
                    __pipeline_memcpy_async(dst + i * 64 + q * 4,
                                            src + (size_t)i * V_ * 64 + q * 4, 16);
                }
            }
            __pipeline_commit();
        }

        const float* S = sl + (t % 3) * 4096;

        if (half == 0) {
            float hm = sh_h[j] * g_ml[t * 64 + j];
            sh_hm[j] = hm;
            g_HM[((size_t)b * T_ + t) * 64 + j] = hm;
        }
        __syncthreads();

        // matvec: h_new[j] = sum_i hm[i] * S[i][j]  (i split across halves)
        float a0 = 0.f, a1 = 0.f, a2 = 0.f, a3 = 0.f;
        int base = half * 32;
#pragma unroll
        for (int u = 0; u < 8; u++) {
            a0 += sh_hm[base + u]      * S[(base + u) * 64 + j];
            a1 += sh_hm[base + 8 + u]  * S[(base + 8 + u) * 64 + j];
            a2 += sh_hm[base + 16 + u] * S[(base + 16 + u) * 64 + j];
            a3 += sh_hm[base + 24 + u] * S[(base + 24 + u) * 64 + j];
        }
        part[half][j] = (a0 + a1) + (a2 + a3);
        __syncthreads();

        if (half == 0) {
            float hv = (part[0][j] + part[1][j]) * g_mr[t * 64 + j];
            float s1 = hv, s2 = hv * hv;
#pragma unroll
            for (int k = 16; k > 0; k >>= 1) {
                s1 += __shfl_xor_sync(0xffffffffu, s1, k);
                s2 += __shfl_xor_sync(0xffffffffu, s2, k);
            }
            int w = j >> 5;
            if ((j & 31) == 0) { red[w] = s1; red[2 + w] = s2; }
            part[0][j] = hv;
        }
        __syncthreads();
        if (half == 0) {
            float hv = part[0][j];
            float tot = red[0] + red[1], tot2 = red[2] + red[3];
            float mu = tot * (1.0f / 64.0f);
            float var = tot2 * (1.0f / 64.0f) - mu * mu;
            sh_h[j] = (hv - mu) * rsqrtf(var + LN_EPS_) * ln_gamma[j] + ln_beta[j];
        }
        __syncthreads();
    }
}

// ---------------- kernel 3: factorized logits + fused partial logsumexp ----------------
// Block tile: 32 t x 64 v, all 8 b. Loop i=0..63:
//   core_r[t,v] = sum_j mr[t,j]*core[i,v,j]   (register-tiled 2t x 4v per thread)
//   acc[b,t,v] += h_mod[b,t,i] * core_r[t,v]
// Epilogue: + bias, per-row (b,t) max/sum-exp over the 64 v's -> partials; target gather.
#define S_CORE_PITCH 68      // 64 + 4 pad: conflict-free LDS.128 with v = tx + 16*w mapping
#define S_HM_PITCH   65

__global__ void __launch_bounds__(256) k_gemm(const float* __restrict__ core,
                                              const float* __restrict__ output_bias,
                                              const int* __restrict__ target_ids) {
    extern __shared__ float smem[];
    float* s_core = smem;                               // 2 * 64 * 68 = 8704
    float* s_mr   = smem + 2 * 64 * S_CORE_PITCH;       // 2048
    float* s_hm   = s_mr + 2048;                        // 8*32*65 = 16640
    float* s_bias = s_hm + 8 * 32 * S_HM_PITCH;         // 64

    int tid = threadIdx.x;
    int bt = blockIdx.x & 15;        // t-tile (16 tiles of 32)
    int bv = blockIdx.x >> 4;        // v-tile (500 tiles of 64)
    int t0 = bt * 32, v0 = bv * 64;

    for (int idx = tid; idx < 2048; idx += 256) s_mr[idx] = g_mr[t0 * 64 + idx];
    for (int b = 0; b < 8; b++) {
        const float* src = g_HM + ((size_t)b * T_ + t0) * 64;
        for (int idx = tid; idx < 2048; idx += 256) {
            int tt = idx >> 6, i = idx & 63;
            s_hm[(b * 32 + tt) * S_HM_PITCH + i] = src[idx];
        }
    }
    if (tid < 64) s_bias[tid] = output_bias[v0 + tid];

    // prefetch core slice for i=0 (contiguous 16KB: core[0, v0:v0+64, :])
    {
        const float* src = core + (size_t)v0 * 64;
        for (int c = tid; c < 1024; c += 256) {
            int v = c >> 4, q = c & 15;
            __pipeline_memcpy_async(s_core + v * S_CORE_PITCH + q * 4, src + c * 4, 16);
        }
        __pipeline_commit();
    }

    int tx = tid & 15, ty = tid >> 4;
    int tl0 = ty * 2, tl1 = tl0 + 1;

    float acc[8][2][4];
#pragma unroll
    for (int b = 0; b < 8; b++)
#pragma unroll
        for (int u = 0; u < 2; u++)
#pragma unroll
            for (int w = 0; w < 4; w++) acc[b][u][w] = 0.f;

    for (int i = 0; i < 64; i++) {
        __pipeline_wait_prior(0);
        __syncthreads();
        int buf = i & 1;
        if (i + 1 < 64) {
            const float* src = core + ((size_t)(i + 1) * V_ + v0) * 64;
            float* dst = s_core + (buf ^ 1) * 64 * S_CORE_PITCH;
            for (int c = tid; c < 1024; c += 256) {
                int v = c >> 4, q = c & 15;
                __pipeline_memcpy_async(dst + v * S_CORE_PITCH + q * 4, src + c * 4, 16);
            }
        }
        __pipeline_commit();

        const float4* mr4 = (const float4*)s_mr;
        const float*  cb  = s_core + buf * 64 * S_CORE_PITCH;

        float cr[2][4] = {{0.f,0.f,0.f,0.f},{0.f,0.f,0.f,0.f}};
#pragma unroll
        for (int j4 = 0; j4 < 16; j4++) {
            float4 m0 = mr4[tl0 * 16 + j4];
            float4 m1 = mr4[tl1 * 16 + j4];
#pragma unroll
            for (int w = 0; w < 4; w++) {
                float4 c = *(const float4*)(cb + (tx + 16 * w) * S_CORE_PITCH + j4 * 4);
                cr[0][w] += m0.x * c.x + m0.y * c.y + m0.z * c.z + m0.w * c.w;
                cr[1][w] += m1.x * c.x + m1.y * c.y + m1.z * c.z + m1.w * c.w;
            }
        }
#pragma unroll
        for (int b = 0; b < 8; b++) {
            float h0v = s_hm[(b * 32 + tl0) * S_HM_PITCH + i];
            float h1v = s_hm[(b * 32 + tl1) * S_HM_PITCH + i];
#pragma unroll
            for (int w = 0; w < 4; w++) {
                acc[b][0][w] += h0v * cr[0][w];
                acc[b][1][w] += h1v * cr[1][w];
            }
        }
    }

    // epilogue: bias + per-row partial logsumexp over this tile's 64 v's
#pragma unroll 1
    for (int b = 0; b < 8; b++) {
#pragma unroll
        for (int u = 0; u < 2; u++) {
            int tg = t0 + tl0 + u;
            int row = b * T_ + tg;
            float l[4];
#pragma unroll
            for (int w = 0; w < 4; w++) l[w] = acc[b][u][w] + s_bias[tx + 16 * w];
            float m = fmaxf(fmaxf(l[0], l[1]), fmaxf(l[2], l[3]));
#pragma unroll
            for (int k = 8; k > 0; k >>= 1)
                m = fmaxf(m, __shfl_xor_sync(0xffffffffu, m, k));
            float s = expf(l[0] - m) + expf(l[1] - m) + expf(l[2] - m) + expf(l[3] - m);
#pragma unroll
            for (int k = 8; k > 0; k >>= 1)
                s += __shfl_xor_sync(0xffffffffu, s, k);
            if (tx == 0) {
                g_pmax[(size_t)row * NVB_ + bv] = m;
                g_psum[(size_t)row * NVB_ + bv] = s;
            }
            int tgt = target_ids[row];
#pragma unroll
            for (int w = 0; w < 4; w++)
                if (v0 + tx + 16 * w == tgt) g_tgt[row] = l[w];
        }
    }
}

// ---------------- kernel 4: per-row logsumexp combine + per-row loss ----------------
__global__ void k_lse() {
    int row = blockIdx.x * 8 + (threadIdx.x >> 5);
    int lane = threadIdx.x & 31;
    const float* pm = g_pmax + (size_t)row * NVB_;
    const float* ps = g_psum + (size_t)row * NVB_;
    float m = -1e30f;
    for (int p = lane; p < NVB_; p += 32) m = fmaxf(m, pm[p]);
#pragma unroll
    for (int k = 16; k > 0; k >>= 1) m = fmaxf(m, __shfl_xor_sync(0xffffffffu, m, k));
    float s = 0.f;
    for (int p = lane; p < NVB_; p += 32) s += ps[p] * expf(pm[p] - m);
#pragma unroll
    for (int k = 16; k > 0; k >>= 1) s += __shfl_xor_sync(0xffffffffu, s, k);
    if (lane == 0) g_rowloss[row] = (m + logf(s)) - g_tgt[row];
}

// ---------------- kernel 5: mean over 4096 rows -> d_out[0] ----------------
__global__ void k_final(float* __restrict__ out) {
    int tid = threadIdx.x;   // 1024
    float s = g_rowloss[tid] + g_rowloss[tid + 1024] +
              g_rowloss[tid + 2048] + g_rowloss[tid + 3072];
    __shared__ float red[32];
#pragma unroll
    for (int k = 16; k > 0; k >>= 1) s += __shfl_xor_sync(0xffffffffu, s, k);
    if ((tid & 31) == 0) red[tid >> 5] = s;
    __syncthreads();
    if (tid < 32) {
        float v = red[tid];
#pragma unroll
        for (int k = 16; k > 0; k >>= 1) v += __shfl_xor_sync(0xffffffffu, v, k);
        if (tid == 0) out[0] = v * (1.0f / (float)BT_);
    }
}

// ---------------- launch ----------------
extern "C" void kernel_launch(void* const* d_in, const int* in_sizes, int n_in,
                              void* d_out, int out_size) {
    const int*   input_ids   = (const int*)d_in[0];
    const int*   target_ids  = (const int*)d_in[1];
    const float* core        = (const float*)d_in[2];
    const float* h0          = (const float*)d_in[3];
    const float* pos_embed   = (const float*)d_in[4];
    const float* W1          = (const float*)d_in[5];
    const float* b1          = (const float*)d_in[6];
    const float* W2          = (const float*)d_in[7];
    const float* b2          = (const float*)d_in[8];
    const float* output_bias = (const float*)d_in[9];
    const float* ln_gamma    = (const float*)d_in[10];
    const float* ln_beta     = (const float*)d_in[11];

    int smem_scan = 3 * 4096 * (int)sizeof(float);                         // 48 KB
    int smem_gemm = (2 * 64 * S_CORE_PITCH + 2048 + 8 * 32 * S_HM_PITCH + 64)
                    * (int)sizeof(float);                                   // ~107 KB
    cudaFuncSetAttribute(k_scan, cudaFuncAttributeMaxDynamicSharedMemorySize, smem_scan);
    cudaFuncSetAttribute(k_gemm, cudaFuncAttributeMaxDynamicSharedMemorySize, smem_gemm);

    k_mod<<<T_, 128>>>(pos_embed, W1, b1, W2, b2);
    k_scan<<<B_, 128, smem_scan>>>(input_ids, core, h0, ln_gamma, ln_beta);
    k_gemm<<<16 * NVB_, 256, smem_gemm>>>(core, output_bias, target_ids);
    k_lse<<<BT_ / 8, 256>>>();
    k_final<<<1, 1024>>>((float*)d_out);
}

// round 4
// speedup vs baseline: 2.9226x; 2.9226x over previous
#include <cuda_runtime.h>
#include <cuda_bf16.h>
#include <cuda_pipeline.h>
#include <math.h>

#define V_   32000
#define CHI_ 64
#define T_   512
#define B_   8
#define BT_  4096
#define NVB_ 1000          // v-tiles of 32
#define LN_EPS_ 1e-5f

// ---------------- scratch (static device memory; no allocations) ----------------
__device__ float g_ml[T_ * CHI_];
__device__ float g_mr[T_ * CHI_];
__device__ float g_HMt[CHI_ * B_ * T_];                 // h_mod transposed: [i][b][t]
__device__ __align__(16) __nv_bfloat16 g_core_hi[(size_t)CHI_ * V_ * CHI_];  // [i][v][j]
__device__ __align__(16) __nv_bfloat16 g_core_lo[(size_t)CHI_ * V_ * CHI_];
__device__ float g_pmax[(size_t)BT_ * NVB_];
__device__ float g_psum[(size_t)BT_ * NVB_];
__device__ float g_tgt[BT_];
__device__ float g_rowloss[BT_];

// ---------------- PTX helpers (base sm_103-safe: ldmatrix + mma.sync) ----------------
__device__ __forceinline__ uint32_t smem_u32(const void* p) {
    uint32_t a;
    asm("{ .reg .u64 t; cvta.to.shared.u64 t, %1; cvt.u32.u64 %0, t; }" : "=r"(a) : "l"(p));
    return a;
}
__device__ __forceinline__ void ldsm_x4(uint32_t* r, uint32_t addr) {
    asm volatile("ldmatrix.sync.aligned.m8n8.x4.shared.b16 {%0,%1,%2,%3}, [%4];"
                 : "=r"(r[0]), "=r"(r[1]), "=r"(r[2]), "=r"(r[3]) : "r"(addr));
}
__device__ __forceinline__ void mma_bf16(float* d, const uint32_t* a, const uint32_t* b) {
    asm volatile("mma.sync.aligned.m16n8k16.row.col.f32.bf16.bf16.f32 "
                 "{%0,%1,%2,%3}, {%4,%5,%6,%7}, {%8,%9}, {%0,%1,%2,%3};"
                 : "+f"(d[0]), "+f"(d[1]), "+f"(d[2]), "+f"(d[3])
                 : "r"(a[0]), "r"(a[1]), "r"(a[2]), "r"(a[3]), "r"(b[0]), "r"(b[1]));
}

// ---------------- kernel 1: modulators ml, mr ----------------
__global__ void k_mod(const float* __restrict__ pos_embed,
                      const float* __restrict__ W1, const float* __restrict__ b1,
                      const float* __restrict__ W2, const float* __restrict__ b2) {
    int t = blockIdx.x;
    int k = threadIdx.x;             // 128 threads
    __shared__ float sp[64];
    __shared__ float sm[128];
    if (k < 64) sp[k] = pos_embed[t * 64 + k];
    __syncthreads();
    float s = b1[k];
#pragma unroll
    for (int p = 0; p < 64; p++) s += sp[p] * W1[p * 128 + k];
    float g = 0.5f * s * (1.0f + erff(s * 0.7071067811865476f));
    sm[k] = g;
    __syncthreads();
    float m = b2[k];
#pragma unroll
    for (int q = 0; q < 128; q++) m += sm[q] * W2[q * 128 + k];
    float v = 1.0f + 0.5f * tanhf(m);
    if (k < 64) g_ml[t * 64 + k] = v;
    else        g_mr[t * 64 + (k - 64)] = v;
}

// ---------------- kernel 2 (fused): blocks 0-7 = sequential scan; rest = core bf16 split ----------------
#define NSPLIT_ 64000      // 131072000 elems / 8 per thread / 256 threads

__global__ void __launch_bounds__(256) k_fused(const int* __restrict__ input_ids,
                                               const float* __restrict__ core,
                                               const float* __restrict__ h0,
                                               const float* __restrict__ ln_gamma,
                                               const float* __restrict__ ln_beta) {
    int tid = threadIdx.x;
    if (blockIdx.x >= 8) {
        // ---- split part: fp32 core -> bf16 hi/lo, plain [i][v][j] layout ----
        size_t e0 = ((size_t)(blockIdx.x - 8) * 256 + tid) * 8;
        float4 x0 = *(const float4*)(core + e0);
        float4 x1 = *(const float4*)(core + e0 + 4);
        float xs[8] = {x0.x, x0.y, x0.z, x0.w, x1.x, x1.y, x1.z, x1.w};
        unsigned short hb[8], lb[8];
#pragma unroll
        for (int q = 0; q < 8; q++) {
            __nv_bfloat16 h = __float2bfloat16_rn(xs[q]);
            __nv_bfloat16 l = __float2bfloat16_rn(xs[q] - __bfloat162float(h));
            hb[q] = __bfloat16_as_ushort(h);
            lb[q] = __bfloat16_as_ushort(l);
        }
        uint4 ph, pl;
        ph.x = (uint32_t)hb[0] | ((uint32_t)hb[1] << 16);
        ph.y = (uint32_t)hb[2] | ((uint32_t)hb[3] << 16);
        ph.z = (uint32_t)hb[4] | ((uint32_t)hb[5] << 16);
        ph.w = (uint32_t)hb[6] | ((uint32_t)hb[7] << 16);
        pl.x = (uint32_t)lb[0] | ((uint32_t)lb[1] << 16);
        pl.y = (uint32_t)lb[2] | ((uint32_t)lb[3] << 16);
        pl.z = (uint32_t)lb[4] | ((uint32_t)lb[5] << 16);
        pl.w = (uint32_t)lb[6] | ((uint32_t)lb[7] << 16);
        *(uint4*)(g_core_hi + e0) = ph;
        *(uint4*)(g_core_lo + e0) = pl;
        return;
    }

    // ---- scan part: one block per batch, 256 threads ----
    extern __shared__ float sl[];    // 3 * 4096 floats
    __shared__ float sh_h[64];
    __shared__ float sh_hm[64];
    __shared__ float part[4][64];
    __shared__ float red[4];

    int b = blockIdx.x;
    int j = tid & 63, q4 = tid >> 6;

    if (q4 == 0) sh_h[j] = h0[j];

    for (int pf = 0; pf < 2; pf++) {
        int x = input_ids[b * T_ + pf];
        const float* src = core + (size_t)x * 64;
        float* dst = sl + pf * 4096;
        for (int c = tid; c < 1024; c += 256) {
            int i = c >> 4, q = c & 15;
            __pipeline_memcpy_async(dst + i * 64 + q * 4,
                                    src + (size_t)i * V_ * 64 + q * 4, 16);
        }
        __pipeline_commit();
    }

    for (int t = 0; t < T_; t++) {
        __pipeline_wait_prior(1);
        __syncthreads();
        {
            int tn = t + 2;
            if (tn < T_) {
                int x = input_ids[b * T_ + tn];
                const float* src = core + (size_t)x * 64;
                float* dst = sl + (tn % 3) * 4096;
                for (int c = tid; c < 1024; c += 256) {
                    int i = c >> 4, q = c & 15;
                    __pipeline_memcpy_async(dst + i * 64 + q * 4,
                                            src + (size_t)i * V_ * 64 + q * 4, 16);
                }
            }
            __pipeline_commit();
        }

        const float* S = sl + (t % 3) * 4096;

        if (q4 == 0) {
            float hm = sh_h[j] * g_ml[t * 64 + j];
            sh_hm[j] = hm;
            g_HMt[(j * B_ + b) * T_ + t] = hm;     // [i][b][t]
        }
        __syncthreads();

        // matvec: i split across 4 quarters of 16
        float a0 = 0.f, a1 = 0.f, a2 = 0.f, a3 = 0.f;
        int base = q4 * 16;
#pragma unroll
        for (int u = 0; u < 4; u++) {
            a0 += sh_hm[base + u]      * S[(base + u) * 64 + j];
            a1 += sh_hm[base + 4 + u]  * S[(base + 4 + u) * 64 + j];
            a2 += sh_hm[base + 8 + u]  * S[(base + 8 + u) * 64 + j];
            a3 += sh_hm[base + 12 + u] * S[(base + 12 + u) * 64 + j];
        }
        part[q4][j] = (a0 + a1) + (a2 + a3);
        __syncthreads();

        if (q4 == 0) {
            float hv = (part[0][j] + part[1][j] + part[2][j] + part[3][j]) * g_mr[t * 64 + j];
            float s1 = hv, s2 = hv * hv;
#pragma unroll
            for (int k = 16; k > 0; k >>= 1) {
                s1 += __shfl_xor_sync(0xffffffffu, s1, k);
                s2 += __shfl_xor_sync(0xffffffffu, s2, k);
            }
            int w = j >> 5;
            if ((j & 31) == 0) { red[w] = s1; red[2 + w] = s2; }
            part[0][j] = hv;
        }
        __syncthreads();
        if (q4 == 0) {
            float hv = part[0][j];
            float tot = red[0] + red[1], tot2 = red[2] + red[3];
            float mu = tot * (1.0f / 64.0f);
            float var = tot2 * (1.0f / 64.0f) - mu * mu;
            sh_h[j] = (hv - mu) * rsqrtf(var + LN_EPS_) * ln_gamma[j] + ln_beta[j];
        }
        __syncthreads();
    }
}

// ---------------- kernel 3: mma.sync factorized logits + fused partial logsumexp ----------------
// Block: 64 t x 32 v, all 8 b; 256 threads (8 warps: 4 t-groups x 2 v-halves).
// Per i: CR(64x32) = mr @ core_i^T via bf16-split mma.sync -> smem; SIMT: acc[b] += h*CR.
#define O_MRH  0          // bf16 64 x 72
#define O_MRL  9216
#define O_CORE 18432      // [buf][split] 4 x (32 x 72 bf16 = 4608 B)
#define O_H    36864      // [buf] 8 x 64 floats  (2 x 2048 B)
#define O_CR   40960      // 64 x 36 floats = 9216 B
#define SMEM_G 50176

__global__ void __launch_bounds__(256, 2) k_gemm(const float* __restrict__ output_bias,
                                                 const int* __restrict__ target_ids) {
    extern __shared__ char smr[];
    uint32_t sb = smem_u32(smr);
    int tid = threadIdx.x;
    int l = tid & 31, w = tid >> 5;
    int tw = w >> 1, vw = w & 1;
    int t0 = blockIdx.x * 64;
    int vb = blockIdx.y, v0 = vb * 32;

    // mr tile -> bf16 hi/lo (padded pitch 72)
    {
        __nv_bfloat16* mrh = (__nv_bfloat16*)(smr + O_MRH);
        __nv_bfloat16* mrl = (__nv_bfloat16*)(smr + O_MRL);
        for (int e = tid; e < 4096; e += 256) {
            int r = e >> 6, c = e & 63;
            float x = g_mr[(t0 + r) * 64 + c];
            __nv_bfloat16 h = __float2bfloat16_rn(x);
            __nv_bfloat16 lo = __float2bfloat16_rn(x - __bfloat162float(h));
            mrh[r * 72 + c] = h;
            mrl[r * 72 + c] = lo;
        }
    }

    int cr_ = tid >> 3, cc_ = tid & 7;       // core copy role: row 0..31, chunk 0..7
    // prefetch i = 0
    {
        const char* sh_ = (const char*)(g_core_hi + ((size_t)0 * V_ + v0 + cr_) * 64) + cc_ * 16;
        const char* slo = (const char*)(g_core_lo + ((size_t)0 * V_ + v0 + cr_) * 64) + cc_ * 16;
        __pipeline_memcpy_async(smr + O_CORE + 0 * 4608 + (cr_ * 72 + cc_ * 8) * 2, sh_, 16);
        __pipeline_memcpy_async(smr + O_CORE + 1 * 4608 + (cr_ * 72 + cc_ * 8) * 2, slo, 16);
        if (tid < 128) {
            int b = tid >> 4, c = tid & 15;
            __pipeline_memcpy_async(smr + O_H + (b * 64 + c * 4) * 4,
                                    g_HMt + ((size_t)0 * B_ + b) * T_ + t0 + c * 4, 16);
        }
        __pipeline_commit();
    }

    // ldmatrix lane address components (row-major A: mr rows; "col" B: core n-major rows)
    uint32_t a_off = (uint32_t)(((tw * 16 + (l & 15)) * 72 + (l >> 4) * 8) * 2);
    uint32_t b_off = (uint32_t)(((vw * 16 + (l & 7) + ((l >> 4) & 1) * 8) * 72
                                 + ((l >> 3) & 1) * 8) * 2);
    uint32_t ah_base = sb + O_MRH + a_off;
    uint32_t al_base = sb + O_MRL + a_off;

    float* CR = (float*)(smr + O_CR);
    float* Hs = (float*)(smr + O_H);
    int tl = tid & 63, vg = tid >> 6;

    float acc[8][8];
#pragma unroll
    for (int b = 0; b < 8; b++)
#pragma unroll
        for (int c = 0; c < 8; c++) acc[b][c] = 0.f;

#pragma unroll 1
    for (int i = 0; i < 64; i++) {
        int nb = (i + 1) & 1;
        if (i + 1 < 64) {
            const char* sh_ = (const char*)(g_core_hi + ((size_t)(i + 1) * V_ + v0 + cr_) * 64) + cc_ * 16;
            const char* slo = (const char*)(g_core_lo + ((size_t)(i + 1) * V_ + v0 + cr_) * 64) + cc_ * 16;
            __pipeline_memcpy_async(smr + O_CORE + (nb * 2 + 0) * 4608 + (cr_ * 72 + cc_ * 8) * 2, sh_, 16);
            __pipeline_memcpy_async(smr + O_CORE + (nb * 2 + 1) * 4608 + (cr_ * 72 + cc_ * 8) * 2, slo, 16);
            if (tid < 128) {
                int b = tid >> 4, c = tid & 15;
                __pipeline_memcpy_async(smr + O_H + nb * 2048 + (b * 64 + c * 4) * 4,
                                        g_HMt + ((size_t)(i + 1) * B_ + b) * T_ + t0 + c * 4, 16);
            }
        }
        __pipeline_commit();
        __pipeline_wait_prior(1);
        __syncthreads();                           // buffers for i ready; CR free

        int bf = i & 1;
        uint32_t bh_base = sb + O_CORE + (bf * 2 + 0) * 4608 + b_off;
        uint32_t bl_base = bh_base + 4608;

        float d0[4] = {0.f, 0.f, 0.f, 0.f}, d1[4] = {0.f, 0.f, 0.f, 0.f};
#pragma unroll
        for (int kk = 0; kk < 4; kk++) {
            uint32_t ah[4], al[4], bh[4], bl[4];
            ldsm_x4(ah, ah_base + kk * 32);
            ldsm_x4(al, al_base + kk * 32);
            ldsm_x4(bh, bh_base + kk * 32);
            ldsm_x4(bl, bl_base + kk * 32);
            mma_bf16(d0, ah, bh);     mma_bf16(d1, ah, bh + 2);
            mma_bf16(d0, ah, bl);     mma_bf16(d1, ah, bl + 2);
            mma_bf16(d0, al, bh);     mma_bf16(d1, al, bh + 2);
        }
        // store CR fragment: rows tw*16 + l/4 (+8), cols vw*16 + (l%4)*2 (+8 for d1)
        {
            int rs = tw * 16 + (l >> 2);
            int cs = vw * 16 + (l & 3) * 2;
            *(float2*)&CR[rs * 36 + cs]          = make_float2(d0[0], d0[1]);
            *(float2*)&CR[(rs + 8) * 36 + cs]    = make_float2(d0[2], d0[3]);
            *(float2*)&CR[rs * 36 + cs + 8]      = make_float2(d1[0], d1[1]);
            *(float2*)&CR[(rs + 8) * 36 + cs + 8] = make_float2(d1[2], d1[3]);
        }
        __syncthreads();                           // CR visible

        // stage B: acc[b][c] += h[b,t] * CR[t, vg*8+c]
        {
            float4 c0 = *(float4*)&CR[tl * 36 + vg * 8];
            float4 c1 = *(float4*)&CR[tl * 36 + vg * 8 + 4];
            const float* hb = Hs + bf * 512;
#pragma unroll
            for (int b = 0; b < 8; b++) {
                float hv = hb[b * 64 + tl];
                acc[b][0] += hv * c0.x;  acc[b][1] += hv * c0.y;
                acc[b][2] += hv * c0.z;  acc[b][3] += hv * c0.w;
                acc[b][4] += hv * c1.x;  acc[b][5] += hv * c1.y;
                acc[b][6] += hv * c1.z;  acc[b][7] += hv * c1.w;
            }
        }
        __syncthreads();                           // protect CR + buffers
    }

    // ---------------- epilogue ----------------
    float bias[8];
#pragma unroll
    for (int c = 0; c < 8; c++) bias[c] = output_bias[v0 + vg * 8 + c];

    float2* red = (float2*)CR;                     // [64][4]
#pragma unroll 1
    for (int b = 0; b < 8; b++) {
        float lx[8];
#pragma unroll
        for (int c = 0; c < 8; c++) lx[c] = acc[b][c] + bias[c];
        float m = lx[0];
#pragma unroll
        for (int c = 1; c < 8; c++) m = fmaxf(m, lx[c]);
        float s = 0.f;
#pragma unroll
        for (int c = 0; c < 8; c++) s += expf(lx[c] - m);
        red[tl * 4 + vg] = make_float2(m, s);
        int row = b * T_ + t0 + tl;
        int dv = target_ids[row] - (v0 + vg * 8);
        if (dv >= 0 && dv < 8) g_tgt[row] = lx[dv];
        __syncthreads();
        if (vg == 0) {
            float2 p0 = red[tl * 4 + 0], p1 = red[tl * 4 + 1];
            float2 p2 = red[tl * 4 + 2], p3 = red[tl * 4 + 3];
            float M = fmaxf(fmaxf(p0.x, p1.x), fmaxf(p2.x, p3.x));
            float S = p0.y * expf(p0.x - M) + p1.y * expf(p1.x - M)
                    + p2.y * expf(p2.x - M) + p3.y * expf(p3.x - M);
            g_pmax[(size_t)row * NVB_ + vb] = M;
            g_psum[(size_t)row * NVB_ + vb] = S;
        }
        __syncthreads();
    }
}

// ---------------- kernel 4: per-row logsumexp combine ----------------
__global__ void k_lse() {
    int row = blockIdx.x * 8 + (threadIdx.x >> 5);
    int lane = threadIdx.x & 31;
    const float* pm = g_pmax + (size_t)row * NVB_;
    const float* ps = g_psum + (size_t)row * NVB_;
    float m = -1e30f;
    for (int p = lane; p < NVB_; p += 32) m = fmaxf(m, pm[p]);
#pragma unroll
    for (int k = 16; k > 0; k >>= 1) m = fmaxf(m, __shfl_xor_sync(0xffffffffu, m, k));
    float s = 0.f;
    for (int p = lane; p < NVB_; p += 32) s += ps[p] * expf(pm[p] - m);
#pragma unroll
    for (int k = 16; k > 0; k >>= 1) s += __shfl_xor_sync(0xffffffffu, s, k);
    if (lane == 0) g_rowloss[row] = (m + logf(s)) - g_tgt[row];
}

// ---------------- kernel 5: mean ----------------
__global__ void k_final(float* __restrict__ out) {
    int tid = threadIdx.x;   // 1024
    float s = g_rowloss[tid] + g_rowloss[tid + 1024] +
              g_rowloss[tid + 2048] + g_rowloss[tid + 3072];
    __shared__ float red[32];
#pragma unroll
    for (int k = 16; k > 0; k >>= 1) s += __shfl_xor_sync(0xffffffffu, s, k);
    if ((tid & 31) == 0) red[tid >> 5] = s;
    __syncthreads();
    if (tid < 32) {
        float v = red[tid];
#pragma unroll
        for (int k = 16; k > 0; k >>= 1) v += __shfl_xor_sync(0xffffffffu, v, k);
        if (tid == 0) out[0] = v * (1.0f / (float)BT_);
    }
}

// ---------------- launch ----------------
extern "C" void kernel_launch(void* const* d_in, const int* in_sizes, int n_in,
                              void* d_out, int out_size) {
    const int*   input_ids   = (const int*)d_in[0];
    const int*   target_ids  = (const int*)d_in[1];
    const float* core        = (const float*)d_in[2];
    const float* h0          = (const float*)d_in[3];
    const float* pos_embed   = (const float*)d_in[4];
    const float* W1          = (const float*)d_in[5];
    const float* b1          = (const float*)d_in[6];
    const float* W2          = (const float*)d_in[7];
    const float* b2          = (const float*)d_in[8];
    const float* output_bias = (const float*)d_in[9];
    const float* ln_gamma    = (const float*)d_in[10];
    const float* ln_beta     = (const float*)d_in[11];

    int smem_fused = 3 * 4096 * (int)sizeof(float);       // 48 KB
    cudaFuncSetAttribute(k_fused, cudaFuncAttributeMaxDynamicSharedMemorySize, smem_fused);
    cudaFuncSetAttribute(k_gemm, cudaFuncAttributeMaxDynamicSharedMemorySize, SMEM_G);

    k_mod<<<T_, 128>>>(pos_embed, W1, b1, W2, b2);
    k_fused<<<8 + NSPLIT_, 256, smem_fused>>>(input_ids, core, h0, ln_gamma, ln_beta);
    dim3 g(8, NVB_);
    k_gemm<<<g, 256, SMEM_G>>>(output_bias, target_ids);
    k_lse<<<BT_ / 8, 256>>>();
    k_final<<<1, 1024>>>((float*)d_out);
}

// round 6
// speedup vs baseline: 4.7694x; 1.6319x over previous
#include <cuda_runtime.h>
#include <cuda_bf16.h>
#include <cuda_pipeline.h>
#include <math.h>

#define V_   32000
#define CHI_ 64
#define T_   512
#define B_   8
#define BT_  4096
#define NVB_ 1000          // v-tiles of 32
#define LN_EPS_ 1e-5f

// ---------------- scratch (static device memory; no allocations) ----------------
__device__ float g_ml[T_ * CHI_];
__device__ float g_mr[T_ * CHI_];
__device__ float g_HM2[CHI_ * T_ * B_];                 // h_mod: [i][t][b]
__device__ __align__(16) __nv_bfloat16 g_core_hi[(size_t)CHI_ * V_ * CHI_];  // [i][v][j]
__device__ float g_pmax[(size_t)BT_ * NVB_];
__device__ float g_psum[(size_t)BT_ * NVB_];
__device__ float g_tgt[BT_];
__device__ float g_rowloss[BT_];

// ---------------- PTX helpers (base sm_103-safe) ----------------
__device__ __forceinline__ uint32_t smem_u32(const void* p) {
    uint32_t a;
    asm("{ .reg .u64 t; cvta.to.shared.u64 t, %1; cvt.u32.u64 %0, t; }" : "=r"(a) : "l"(p));
    return a;
}
__device__ __forceinline__ void ldsm_x4(uint32_t* r, uint32_t addr) {
    asm volatile("ldmatrix.sync.aligned.m8n8.x4.shared.b16 {%0,%1,%2,%3}, [%4];"
                 : "=r"(r[0]), "=r"(r[1]), "=r"(r[2]), "=r"(r[3]) : "r"(addr));
}
__device__ __forceinline__ void mma_bf16(float* d, const uint32_t* a, const uint32_t* b) {
    asm volatile("mma.sync.aligned.m16n8k16.row.col.f32.bf16.bf16.f32 "
                 "{%0,%1,%2,%3}, {%4,%5,%6,%7}, {%8,%9}, {%0,%1,%2,%3};"
                 : "+f"(d[0]), "+f"(d[1]), "+f"(d[2]), "+f"(d[3])
                 : "r"(a[0]), "r"(a[1]), "r"(a[2]), "r"(a[3]), "r"(b[0]), "r"(b[1]));
}
#define FMA2(a, h, c) asm("fma.rn.f32x2 %0, %1, %2, %0;" : "+l"(a) : "l"(h), "l"(c))
#define PACK2(d, x)   asm("mov.b64 %0, {%1, %1};" : "=l"(d) : "f"(x))

// ---------------- kernel 1: modulators ml, mr ----------------
__global__ void k_mod(const float* __restrict__ pos_embed,
                      const float* __restrict__ W1, const float* __restrict__ b1,
                      const float* __restrict__ W2, const float* __restrict__ b2) {
    int t = blockIdx.x;
    int k = threadIdx.x;             // 128 threads
    __shared__ float sp[64];
    __shared__ float sm[128];
    if (k < 64) sp[k] = pos_embed[t * 64 + k];
    __syncthreads();
    float s = b1[k];
#pragma unroll
    for (int p = 0; p < 64; p++) s += sp[p] * W1[p * 128 + k];
    float g = 0.5f * s * (1.0f + erff(s * 0.7071067811865476f));
    sm[k] = g;
    __syncthreads();
    float m = b2[k];
#pragma unroll
    for (int q = 0; q < 128; q++) m += sm[q] * W2[q * 128 + k];
    float v = 1.0f + 0.5f * tanhf(m);
    if (k < 64) g_ml[t * 64 + k] = v;
    else        g_mr[t * 64 + (k - 64)] = v;
}

// ---------------- kernel 2 (fused): blocks 0-7 = sequential scan; rest = core bf16 convert ----------------
#define NSPLIT_ 64000      // 131072000 elems / 8 per thread / 256 threads

__global__ void __launch_bounds__(256) k_fused(const int* __restrict__ input_ids,
                                               const float* __restrict__ core,
                                               const float* __restrict__ h0,
                                               const float* __restrict__ ln_gamma,
                                               const float* __restrict__ ln_beta) {
    int tid = threadIdx.x;
    if (blockIdx.x >= 8) {
        // ---- convert: fp32 core -> bf16, plain [i][v][j] layout ----
        size_t e0 = ((size_t)(blockIdx.x - 8) * 256 + tid) * 8;
        float4 x0 = *(const float4*)(core + e0);
        float4 x1 = *(const float4*)(core + e0 + 4);
        float xs[8] = {x0.x, x0.y, x0.z, x0.w, x1.x, x1.y, x1.z, x1.w};
        unsigned short hb[8];
#pragma unroll
        for (int q = 0; q < 8; q++)
            hb[q] = __bfloat16_as_ushort(__float2bfloat16_rn(xs[q]));
        uint4 ph;
        ph.x = (uint32_t)hb[0] | ((uint32_t)hb[1] << 16);
        ph.y = (uint32_t)hb[2] | ((uint32_t)hb[3] << 16);
        ph.z = (uint32_t)hb[4] | ((uint32_t)hb[5] << 16);
        ph.w = (uint32_t)hb[6] | ((uint32_t)hb[7] << 16);
        *(uint4*)(g_core_hi + e0) = ph;
        return;
    }

    // ---- scan part: one block per batch, 256 threads ----
    extern __shared__ float sl[];    // 3 * 4096 floats
    __shared__ float sh_h[64];
    __shared__ float sh_hm[64];
    __shared__ float part[4][64];
    __shared__ float red[4];

    int b = blockIdx.x;
    int j = tid & 63, q4 = tid >> 6;

    if (q4 == 0) sh_h[j] = h0[j];

    for (int pf = 0; pf < 2; pf++) {
        int x = input_ids[b * T_ + pf];
        const float* src = core + (size_t)x * 64;
        float* dst = sl + pf * 4096;
        for (int c = tid; c < 1024; c += 256) {
            int i = c >> 4, q = c & 15;
            __pipeline_memcpy_async(dst + i * 64 + q * 4,
                                    src + (size_t)i * V_ * 64 + q * 4, 16);
        }
        __pipeline_commit();
    }

    for (int t = 0; t < T_; t++) {
        __pipeline_wait_prior(1);
        __syncthreads();
        {
            int tn = t + 2;
            if (tn < T_) {
                int x = input_ids[b * T_ + tn];
                const float* src = core + (size_t)x * 64;
                float* dst = sl + (tn % 3) * 4096;
                for (int c = tid; c < 1024; c += 256) {
                    int i = c >> 4, q = c & 15;
                    __pipeline_memcpy_async(dst + i * 64 + q * 4,
                                            src + (size_t)i * V_ * 64 + q * 4, 16);
                }
            }
            __pipeline_commit();
        }

        const float* S = sl + (t % 3) * 4096;

        if (q4 == 0) {
            float hm = sh_h[j] * g_ml[t * 64 + j];
            sh_hm[j] = hm;
            g_HM2[((size_t)j * T_ + t) * B_ + b] = hm;   // [i][t][b]
        }
        __syncthreads();

        float a0 = 0.f, a1 = 0.f, a2 = 0.f, a3 = 0.f;
        int base = q4 * 16;
#pragma unroll
        for (int u = 0; u < 4; u++) {
            a0 += sh_hm[base + u]      * S[(base + u) * 64 + j];
            a1 += sh_hm[base + 4 + u]  * S[(base + 4 + u) * 64 + j];
            a2 += sh_hm[base + 8 + u]  * S[(base + 8 + u) * 64 + j];
            a3 += sh_hm[base + 12 + u] * S[(base + 12 + u) * 64 + j];
        }
        part[q4][j] = (a0 + a1) + (a2 + a3);
        __syncthreads();

        if (q4 == 0) {
            float hv = (part[0][j] + part[1][j] + part[2][j] + part[3][j]) * g_mr[t * 64 + j];
            float s1 = hv, s2 = hv * hv;
#pragma unroll
            for (int k = 16; k > 0; k >>= 1) {
                s1 += __shfl_xor_sync(0xffffffffu, s1, k);
                s2 += __shfl_xor_sync(0xffffffffu, s2, k);
            }
            int w = j >> 5;
            if ((j & 31) == 0) { red[w] = s1; red[2 + w] = s2; }
            part[0][j] = hv;
        }
        __syncthreads();
        if (q4 == 0) {
            float hv = part[0][j];
            float tot = red[0] + red[1], tot2 = red[2] + red[3];
            float mu = tot * (1.0f / 64.0f);
            float var = tot2 * (1.0f / 64.0f) - mu * mu;
            sh_h[j] = (hv - mu) * rsqrtf(var + LN_EPS_) * ln_gamma[j] + ln_beta[j];
        }
        __syncthreads();
    }
}

// ---------------- kernel 3: mma.sync factorized logits, register-resident stage B ----------------
// Block: 64 t x 32 v, all 8 b; 256 threads (8 warps: 4 t-groups x 2 v-halves).
// Per i: d-frag (16t x 16v per warp) = mr @ core_i^T (single bf16, fp32 accum);
// stage B in-register: acc2[b-pair][cell] += {h,h-pair} * {cr,cr}.
#define O_A  0            // mr bf16 64 x 72 = 9216 B; reused as red2 (8 KB) in epilogue
#define O_B  9216         // 3 bufs x (32 x 72 bf16 = 4608 B)
#define O_H  23040        // 3 bufs x (64 t x 8 b floats = 2048 B)
#define SMEM_G 29184

__global__ void __launch_bounds__(256, 2) k_gemm(const float* __restrict__ output_bias,
                                                 const int* __restrict__ target_ids) {
    extern __shared__ char smr[];
    uint32_t sb = smem_u32(smr);
    int tid = threadIdx.x;
    int l = tid & 31, w = tid >> 5;
    int tw = w >> 1, vw = w & 1;
    int t0 = blockIdx.x * 64;
    int vb = blockIdx.y, v0 = vb * 32;

    // A: mr tile -> bf16 (pitch 72)
    {
        __nv_bfloat16* mrh = (__nv_bfloat16*)(smr + O_A);
        for (int e = tid; e < 4096; e += 256) {
            int r = e >> 6, c = e & 63;
            mrh[r * 72 + c] = __float2bfloat16_rn(g_mr[(t0 + r) * 64 + c]);
        }
    }

    // prefetch i = 0, 1
    int cr_ = tid >> 3, cc_ = tid & 7;       // core copy: v-row 0..31, 16B chunk 0..7
    for (int pf = 0; pf < 2; pf++) {
        const char* s = (const char*)(g_core_hi + ((size_t)pf * V_ + v0 + cr_) * 64) + cc_ * 16;
        __pipeline_memcpy_async(smr + O_B + pf * 4608 + (cr_ * 72 + cc_ * 8) * 2, s, 16);
        if (tid < 128) {
            int tr = tid >> 1, q = tid & 1;
            __pipeline_memcpy_async(smr + O_H + pf * 2048 + (tr * 8 + q * 4) * 4,
                                    g_HM2 + ((size_t)pf * T_ + t0 + tr) * 8 + q * 4, 16);
        }
        __pipeline_commit();
    }

    uint32_t a_off = (uint32_t)(((tw * 16 + (l & 15)) * 72 + (l >> 4) * 8) * 2);
    uint32_t b_off = (uint32_t)(((vw * 16 + (l & 7) + ((l >> 4) & 1) * 8) * 72
                                 + ((l >> 3) & 1) * 8) * 2);

    __syncthreads();                          // A smem ready
    uint32_t aA[16];
#pragma unroll
    for (int kk = 0; kk < 4; kk++) ldsm_x4(aA + kk * 4, sb + O_A + a_off + kk * 32);

    int r0 = tw * 16 + (l >> 2);              // d-frag rows r0, r0+8
    int c0 = vw * 16 + 2 * (l & 3);           // d-frag cols c0, c0+1, c0+8, c0+9
    const float* Hs = (const float*)(smr + O_H);

    unsigned long long acc[32];               // [cell 0..7][bpair 0..3]
#pragma unroll
    for (int q = 0; q < 32; q++) acc[q] = 0ull;

#pragma unroll 1
    for (int i = 0; i < 64; i++) {
        __pipeline_wait_prior(1);
        __syncthreads();
        {
            int nx = i + 2;
            if (nx < 64) {
                const char* s = (const char*)(g_core_hi + ((size_t)nx * V_ + v0 + cr_) * 64) + cc_ * 16;
                __pipeline_memcpy_async(smr + O_B + (nx % 3) * 4608 + (cr_ * 72 + cc_ * 8) * 2, s, 16);
                if (tid < 128) {
                    int tr = tid >> 1, q = tid & 1;
                    __pipeline_memcpy_async(smr + O_H + (nx % 3) * 2048 + (tr * 8 + q * 4) * 4,
                                            g_HM2 + ((size_t)nx * T_ + t0 + tr) * 8 + q * 4, 16);
                }
            }
            __pipeline_commit();
        }

        int bf = i % 3;
        uint32_t bb = sb + O_B + bf * 4608 + b_off;
        float d0[4] = {0.f, 0.f, 0.f, 0.f}, d1[4] = {0.f, 0.f, 0.f, 0.f};
#pragma unroll
        for (int kk = 0; kk < 4; kk++) {
            uint32_t bh[4];
            ldsm_x4(bh, bb + kk * 32);
            mma_bf16(d0, aA + kk * 4, bh);
            mma_bf16(d1, aA + kk * 4, bh + 2);
        }

        // stage B: acc2 += {h[b],h[b+1]} * {cr,cr}
        const float* hb0 = Hs + bf * 512 + r0 * 8;   // h[r0][0..7]
        const float* hb1 = hb0 + 64;                 // h[r0+8][0..7]
        unsigned long long h2a[4], h2b[4];
#pragma unroll
        for (int bp = 0; bp < 4; bp++) {
            h2a[bp] = *(const unsigned long long*)(hb0 + bp * 2);
            h2b[bp] = *(const unsigned long long*)(hb1 + bp * 2);
        }
        // cells: 0:(r0,c0) 1:(r0,c0+1) 2:(r0+8,c0) 3:(r0+8,c0+1)
        //        4:(r0,c0+8) 5:(r0,c0+9) 6:(r0+8,c0+8) 7:(r0+8,c0+9)
        unsigned long long c2;
        PACK2(c2, d0[0]);
#pragma unroll
        for (int bp = 0; bp < 4; bp++) FMA2(acc[0 * 4 + bp], h2a[bp], c2);
        PACK2(c2, d0[1]);
#pragma unroll
        for (int bp = 0; bp < 4; bp++) FMA2(acc[1 * 4 + bp], h2a[bp], c2);
        PACK2(c2, d0[2]);
#pragma unroll
        for (int bp = 0; bp < 4; bp++) FMA2(acc[2 * 4 + bp], h2b[bp], c2);
        PACK2(c2, d0[3]);
#pragma unroll
        for (int bp = 0; bp < 4; bp++) FMA2(acc[3 * 4 + bp], h2b[bp], c2);
        PACK2(c2, d1[0]);
#pragma unroll
        for (int bp = 0; bp < 4; bp++) FMA2(acc[4 * 4 + bp], h2a[bp], c2);
        PACK2(c2, d1[1]);
#pragma unroll
        for (int bp = 0; bp < 4; bp++) FMA2(acc[5 * 4 + bp], h2a[bp], c2);
        PACK2(c2, d1[2]);
#pragma unroll
        for (int bp = 0; bp < 4; bp++) FMA2(acc[6 * 4 + bp], h2b[bp], c2);
        PACK2(c2, d1[3]);
#pragma unroll
        for (int bp = 0; bp < 4; bp++) FMA2(acc[7 * 4 + bp], h2b[bp], c2);
    }

    // ---------------- epilogue ----------------
    float bs0 = output_bias[v0 + c0],     bs1 = output_bias[v0 + c0 + 1];
    float bs2 = output_bias[v0 + c0 + 8], bs3 = output_bias[v0 + c0 + 9];

    float2* red2 = (float2*)(smr + O_A);       // [8 b][64 row][2 vw]
#pragma unroll 1
    for (int b = 0; b < 8; b++) {
        int bp = b >> 1, hi = b & 1;
        float lx[8];
#pragma unroll
        for (int cell = 0; cell < 8; cell++) {
            float2 v = *(float2*)&acc[cell * 4 + bp];
            lx[cell] = hi ? v.y : v.x;
        }
        lx[0] += bs0; lx[1] += bs1; lx[2] += bs0; lx[3] += bs1;
        lx[4] += bs2; lx[5] += bs3; lx[6] += bs2; lx[7] += bs3;

        float mA = fmaxf(fmaxf(lx[0], lx[1]), fmaxf(lx[4], lx[5]));   // row r0
        float mB = fmaxf(fmaxf(lx[2], lx[3]), fmaxf(lx[6], lx[7]));   // row r0+8
#pragma unroll
        for (int k = 1; k < 4; k <<= 1) {
            mA = fmaxf(mA, __shfl_xor_sync(0xffffffffu, mA, k));
            mB = fmaxf(mB, __shfl_xor_sync(0xffffffffu, mB, k));
        }
        float sA = expf(lx[0] - mA) + expf(lx[1] - mA) + expf(lx[4] - mA) + expf(lx[5] - mA);
        float sB = expf(lx[2] - mB) + expf(lx[3] - mB) + expf(lx[6] - mB) + expf(lx[7] - mB);
#pragma unroll
        for (int k = 1; k < 4; k <<= 1) {
            sA += __shfl_xor_sync(0xffffffffu, sA, k);
            sB += __shfl_xor_sync(0xffffffffu, sB, k);
        }
        if ((l & 3) == 0) {
            red2[(b * 64 + r0) * 2 + vw]     = make_float2(mA, sA);
            red2[(b * 64 + r0 + 8) * 2 + vw] = make_float2(mB, sB);
        }
        // target gather
        int rg0 = b * T_ + t0 + r0;
        int tg0 = target_ids[rg0] - v0;
        if (tg0 == c0)     g_tgt[rg0] = lx[0];
        if (tg0 == c0 + 1) g_tgt[rg0] = lx[1];
        if (tg0 == c0 + 8) g_tgt[rg0] = lx[4];
        if (tg0 == c0 + 9) g_tgt[rg0] = lx[5];
        int rg1 = rg0 + 8;
        int tg1 = target_ids[rg1] - v0;
        if (tg1 == c0)     g_tgt[rg1] = lx[2];
        if (tg1 == c0 + 1) g_tgt[rg1] = lx[3];
        if (tg1 == c0 + 8) g_tgt[rg1] = lx[6];
        if (tg1 == c0 + 9) g_tgt[rg1] = lx[7];
    }
    __syncthreads();

#pragma unroll
    for (int pass = 0; pass < 2; pass++) {
        int idx = tid + pass * 256;            // 0..511
        int b = idx >> 6, row = idx & 63;
        float2 p0 = red2[(b * 64 + row) * 2 + 0];
        float2 p1 = red2[(b * 64 + row) * 2 + 1];
        float M = fmaxf(p0.x, p1.x);
        float S = p0.y * expf(p0.x - M) + p1.y * expf(p1.x - M);
        int rw = b * T_ + t0 + row;
        g_pmax[(size_t)rw * NVB_ + vb] = M;
        g_psum[(size_t)rw * NVB_ + vb] = S;
    }
}

// ---------------- kernel 4: per-row logsumexp combine ----------------
__global__ void k_lse() {
    int row = blockIdx.x * 8 + (threadIdx.x >> 5);
    int lane = threadIdx.x & 31;
    const float* pm = g_pmax + (size_t)row * NVB_;
    const float* ps = g_psum + (size_t)row * NVB_;
    float m = -1e30f;
    for (int p = lane; p < NVB_; p += 32) m = fmaxf(m, pm[p]);
#pragma unroll
    for (int k = 16; k > 0; k >>= 1) m = fmaxf(m, __shfl_xor_sync(0xffffffffu, m, k));
    float s = 0.f;
    for (int p = lane; p < NVB_; p += 32) s += ps[p] * expf(pm[p] - m);
#pragma unroll
    for (int k = 16; k > 0; k >>= 1) s += __shfl_xor_sync(0xffffffffu, s, k);
    if (lane == 0) g_rowloss[row] = (m + logf(s)) - g_tgt[row];
}

// ---------------- kernel 5: mean ----------------
__global__ void k_final(float* __restrict__ out) {
    int tid = threadIdx.x;   // 1024
    float s = g_rowloss[tid] + g_rowloss[tid + 1024] +
              g_rowloss[tid + 2048] + g_rowloss[tid + 3072];
    __shared__ float red[32];
#pragma unroll
    for (int k = 16; k > 0; k >>= 1) s += __shfl_xor_sync(0xffffffffu, s, k);
    if ((tid & 31) == 0) red[tid >> 5] = s;
    __syncthreads();
    if (tid < 32) {
        float v = red[tid];
#pragma unroll
        for (int k = 16; k > 0; k >>= 1) v += __shfl_xor_sync(0xffffffffu, v, k);
        if (tid == 0) out[0] = v * (1.0f / (float)BT_);
    }
}

// ---------------- launch ----------------
extern "C" void kernel_launch(void* const* d_in, const int* in_sizes, int n_in,
                              void* d_out, int out_size) {
    const int*   input_ids   = (const int*)d_in[0];
    const int*   target_ids  = (const int*)d_in[1];
    const float* core        = (const float*)d_in[2];
    const float* h0          = (const float*)d_in[3];
    const float* pos_embed   = (const float*)d_in[4];
    const float* W1          = (const float*)d_in[5];
    const float* b1          = (const float*)d_in[6];
    const float* W2          = (const float*)d_in[7];
    const float* b2          = (const float*)d_in[8];
    const float* output_bias = (const float*)d_in[9];
    const float* ln_gamma    = (const float*)d_in[10];
    const float* ln_beta     = (const float*)d_in[11];

    int smem_fused = 3 * 4096 * (int)sizeof(float);       // 48 KB
    cudaFuncSetAttribute(k_fused, cudaFuncAttributeMaxDynamicSharedMemorySize, smem_fused);
    cudaFuncSetAttribute(k_gemm, cudaFuncAttributeMaxDynamicSharedMemorySize, SMEM_G);

    k_mod<<<T_, 128>>>(pos_embed, W1, b1, W2, b2);
    k_fused<<<8 + NSPLIT_, 256, smem_fused>>>(input_ids, core, h0, ln_gamma, ln_beta);
    dim3 g(8, NVB_);
    k_gemm<<<g, 256, SMEM_G>>>(output_bias, target_ids);
    k_lse<<<BT_ / 8, 256>>>();
    k_final<<<1, 1024>>>((float*)d_out);
}